// round 15
// baseline (speedup 1.0000x reference)
#include <cuda_runtime.h>
#include <cuda_bf16.h>
#include <cstdint>

#define N_ 50000
#define F_ 128
#define E_ 800000
#define K_ 64
#define L_ 3

using u64 = unsigned long long;

// ---------------------------------------------------------------------------
// Scratch (static device globals — no runtime allocation)
// ---------------------------------------------------------------------------
__device__ float g_m[(size_t)N_ * F_];      // xi, then m (edge adds into it)
__device__ float g_xjall[(size_t)N_ * F_];  // ssp(ssp(x)@Wj+bj)
// bf16-split transposed node weights: [mat 0..8][c 0..127][k 0..127]
//   0=Wi 1=Wj 2..4=Wr1[l] 5..7=Wr2[l] 8=Wf
__device__ __nv_bfloat16 g_wthi[9 * 128 * 128];
__device__ __nv_bfloat16 g_wtlo[9 * 128 * 128];
// bf16-split transposed Wk2f: [c 0..127][k 0..63]
__device__ __nv_bfloat16 g_wkhi[128 * 64];
__device__ __nv_bfloat16 g_wklo[128 * 64];

__device__ __forceinline__ float ssp(float v) {
    float ax = fabsf(v);
    return fmaxf(v, 0.0f) + __logf(1.0f + __expf(-ax)) -
           0.69314718055994530942f;
}
__device__ __forceinline__ float4 ssp4(float4 v) {
    v.x = ssp(v.x); v.y = ssp(v.y); v.z = ssp(v.z); v.w = ssp(v.w);
    return v;
}

__device__ __forceinline__ uint32_t smem_u32(const void* p) {
    uint32_t a;
    asm("{ .reg .u64 t; cvta.to.shared.u64 t, %1; cvt.u32.u64 %0, t; }"
        : "=r"(a) : "l"(p));
    return a;
}

__device__ __forceinline__ void ldsm4(unsigned* r, uint32_t addr) {
    asm volatile(
        "ldmatrix.sync.aligned.m8n8.x4.shared.b16 {%0,%1,%2,%3}, [%4];"
        : "=r"(r[0]), "=r"(r[1]), "=r"(r[2]), "=r"(r[3]) : "r"(addr));
}

__device__ __forceinline__ void mma16816(float* d, const unsigned* a,
                                         const unsigned b0, const unsigned b1) {
    asm volatile(
        "mma.sync.aligned.m16n8k16.row.col.f32.bf16.bf16.f32 "
        "{%0,%1,%2,%3}, {%4,%5,%6,%7}, {%8,%9}, {%0,%1,%2,%3};"
        : "+f"(d[0]), "+f"(d[1]), "+f"(d[2]), "+f"(d[3])
        : "r"(a[0]), "r"(a[1]), "r"(a[2]), "r"(a[3]), "r"(b0), "r"(b1));
}

__device__ __forceinline__ void split4(float4 v, u64& hv, u64& lv) {
    __nv_bfloat162 h01 = __floats2bfloat162_rn(v.x, v.y);
    __nv_bfloat162 h23 = __floats2bfloat162_rn(v.z, v.w);
    __nv_bfloat162 l01 = __floats2bfloat162_rn(
        v.x - __bfloat162float(h01.x), v.y - __bfloat162float(h01.y));
    __nv_bfloat162 l23 = __floats2bfloat162_rn(
        v.z - __bfloat162float(h23.x), v.w - __bfloat162float(h23.y));
    hv = ((u64)*reinterpret_cast<uint32_t*>(&h23) << 32) |
         *reinterpret_cast<uint32_t*>(&h01);
    lv = ((u64)*reinterpret_cast<uint32_t*>(&l23) << 32) |
         *reinterpret_cast<uint32_t*>(&l01);
}

// cp.async helpers
__device__ __forceinline__ void cp16(uint32_t dst, const void* src) {
    asm volatile("cp.async.cg.shared.global [%0], [%1], 16;"
                 :: "r"(dst), "l"(src));
}
#define CP_COMMIT() asm volatile("cp.async.commit_group;" ::: "memory")
#define CP_WAIT1() asm volatile("cp.async.wait_group 1;" ::: "memory")
#define CP_WAIT0() asm volatile("cp.async.wait_group 0;" ::: "memory")

// ---------------------------------------------------------------------------
// Weight packing (one-time)
// ---------------------------------------------------------------------------
__global__ void packw_kernel(const float* __restrict__ Wi,
                             const float* __restrict__ Wj,
                             const float* __restrict__ Wr1,
                             const float* __restrict__ Wr2,
                             const float* __restrict__ Wf,
                             __nv_bfloat16* __restrict__ hi,
                             __nv_bfloat16* __restrict__ lo) {
    int m = blockIdx.y;
    const float* W;
    if (m == 0) W = Wi;
    else if (m == 1) W = Wj;
    else if (m < 5) W = Wr1 + (size_t)(m - 2) * F_ * F_;
    else if (m < 8) W = Wr2 + (size_t)(m - 5) * F_ * F_;
    else W = Wf;
    int i = blockIdx.x * blockDim.x + threadIdx.x;
    if (i < 128 * 128) {
        int c = i >> 7, k = i & 127;
        float f = W[k * 128 + c];
        __nv_bfloat16 h = __float2bfloat16_rn(f);
        __nv_bfloat16 l = __float2bfloat16_rn(f - __bfloat162float(h));
        hi[(size_t)m * 16384 + i] = h;
        lo[(size_t)m * 16384 + i] = l;
    }
}

__global__ void packwk_kernel(const float* __restrict__ W,
                              __nv_bfloat16* __restrict__ hi,
                              __nv_bfloat16* __restrict__ lo) {
    int i = blockIdx.x * blockDim.x + threadIdx.x;
    if (i < 128 * 64) {
        int c = i >> 6, k = i & 63;
        float f = W[k * 128 + c];
        __nv_bfloat16 h = __float2bfloat16_rn(f);
        __nv_bfloat16 l = __float2bfloat16_rn(f - __bfloat162float(h));
        hi[i] = h;
        lo[i] = l;
    }
}

// ---------------------------------------------------------------------------
// Shared GEMM core: 64 rows x 128 cols x K=128, 3-term bf16 split.
// 8 warps = 4 row-groups x 2 col-groups; warp = 16 rows x 64 cols
// (1 m16 x 8 n8), d[8][4]. Layouts proven in rounds 6-11.
// ---------------------------------------------------------------------------
#define TLDA 136
#define ACTPL (64 * TLDA * 2)     // 17408 B per act plane
#define WPL   (128 * TLDA * 2)    // 34816 B per W plane

// prefetch one W matrix (hi+lo) into buffer at dsthi (lo at +WPL); 1 group
__device__ __forceinline__ void prefetch_w(uint32_t dsthi,
                                           const __nv_bfloat16* hi,
                                           const __nv_bfloat16* lo, int tid) {
    uint32_t dstlo = dsthi + WPL;
#pragma unroll
    for (int it = 0; it < 8; ++it) {
        int idx = tid + it * 256;       // 0..2047
        int c = idx >> 4, seg = idx & 15;
        uint32_t off = (uint32_t)(c * TLDA + seg * 8) * 2;
        cp16(dsthi + off, hi + idx * 8);
        cp16(dstlo + off, lo + idx * 8);
    }
    CP_COMMIT();
}

__device__ __forceinline__ void mma_phase(uint32_t smb, uint32_t ahoff,
                                          uint32_t aloff, uint32_t whoff,
                                          uint32_t wloff, int lane,
                                          int warp_m, int warp_n,
                                          float d[8][4]) {
    int a_row = warp_m * 16 + (lane & 15);
    int a_k8 = (lane >> 4) * 8;
    int b_n = warp_n * 64 + (lane >> 4) * 8 + (lane & 7);
    int b_k8 = ((lane >> 3) & 1) * 8;
#pragma unroll
    for (int ks = 0; ks < 8; ++ks) {
        int kb = ks * 16;
        unsigned bh[4][4], bl[4][4], ah[4], al[4];
#pragma unroll
        for (int p = 0; p < 4; ++p) {
            uint32_t boff =
                (uint32_t)((b_n + p * 16) * TLDA + kb + b_k8) * 2;
            ldsm4(bh[p], smb + whoff + boff);
            ldsm4(bl[p], smb + wloff + boff);
        }
        uint32_t aoff = (uint32_t)(a_row * TLDA + kb + a_k8) * 2;
        ldsm4(ah, smb + ahoff + aoff);
        ldsm4(al, smb + aloff + aoff);
#pragma unroll
        for (int term = 0; term < 3; ++term) {
#pragma unroll
            for (int nt = 0; nt < 8; ++nt) {
                const unsigned* af = (term == 2) ? al : ah;
                const unsigned* bf = (term == 1) ? bl[nt >> 1] : bh[nt >> 1];
                mma16816(d[nt], af, bf[(nt & 1) * 2], bf[(nt & 1) * 2 + 1]);
            }
        }
    }
}

// ---------------------------------------------------------------------------
// head: per 64-row CTA, stage split(ssp(x)); GEMM Wi -> m, GEMM Wj -> xjall.
// smem: act hi/lo + 2 double-buffered W pairs = 174080 B -> 1 CTA/SM.
// ---------------------------------------------------------------------------
#define H_ACT_HI 0
#define H_ACT_LO ACTPL
#define H_W      (2 * ACTPL)
#define H_TOTAL  (2 * ACTPL + 2 * 2 * WPL)   // 174080

__global__ __launch_bounds__(256, 1)
void head_kernel(const float* __restrict__ x,
                 const __nv_bfloat16* __restrict__ whi,
                 const __nv_bfloat16* __restrict__ wlo,
                 const float* __restrict__ bi, const float* __restrict__ bj,
                 float* __restrict__ m, float* __restrict__ xjall, int n) {
    extern __shared__ __align__(16) char sm[];
    uint32_t smb = smem_u32(sm);
    int tid = threadIdx.x, wid = tid >> 5, lane = tid & 31;
    int row0 = blockIdx.x * 64;
    int warp_m = wid & 3, warp_n = wid >> 2;

    prefetch_w(smb + H_W, whi, wlo, tid);                       // Wi -> buf0
    prefetch_w(smb + H_W + 2 * WPL, whi + 16384, wlo + 16384, tid);  // Wj

    // stage act = split(ssp(x))
    {
        const float4* X4 = reinterpret_cast<const float4*>(x);
#pragma unroll
        for (int it = 0; it < 8; ++it) {
            int idx = tid + it * 256;
            int row = idx >> 5, k4 = idx & 31;
            float4 v = make_float4(0.f, 0.f, 0.f, 0.f);
            if (row0 + row < n) v = X4[(size_t)(row0 + row) * 32 + k4];
            v = ssp4(v);
            u64 hv, lv;
            split4(v, hv, lv);
            uint32_t off = (uint32_t)(row * TLDA + k4 * 4) * 2;
            *reinterpret_cast<u64*>(sm + H_ACT_HI + off) = hv;
            *reinterpret_cast<u64*>(sm + H_ACT_LO + off) = lv;
        }
    }

#pragma unroll
    for (int g = 0; g < 2; ++g) {
        if (g == 0) CP_WAIT1(); else CP_WAIT0();
        __syncthreads();
        float d[8][4];
#pragma unroll
        for (int nt = 0; nt < 8; ++nt)
#pragma unroll
            for (int q = 0; q < 4; ++q) d[nt][q] = 0.f;
        uint32_t wb = H_W + g * 2 * WPL;
        mma_phase(smb, H_ACT_HI, H_ACT_LO, wb, wb + WPL,
                  lane, warp_m, warp_n, d);

        const float* bias = g ? bj : bi;
        float* C = g ? xjall : m;
        const float2* bias2 = reinterpret_cast<const float2*>(bias);
        float2* C2 = reinterpret_cast<float2*>(C);
#pragma unroll
        for (int half = 0; half < 2; ++half) {
            int r = row0 + warp_m * 16 + (lane >> 2) + half * 8;
            if (r >= n) continue;
#pragma unroll
            for (int nt = 0; nt < 8; ++nt) {
                int c = warp_n * 64 + nt * 8 + (lane & 3) * 2;
                float2 bb = bias2[c >> 1];
                float2 v;
                v.x = ssp(d[nt][half * 2 + 0] + bb.x);
                v.y = ssp(d[nt][half * 2 + 1] + bb.y);
                C2[(size_t)r * 64 + (c >> 1)] = v;
            }
        }
        __syncthreads();
    }
}

// ---------------------------------------------------------------------------
// tail: per 64-row CTA, m resident in smem; 7 fused GEMMs
// (Wr1/Wr2 x3, Wf), W streamed 2-deep via cp.async.
// smem: act(2x17408) + m fp32(64x132x4=33792) + 2 W pairs = 207872 B.
// ---------------------------------------------------------------------------
#define T_ACT_HI 0
#define T_ACT_LO ACTPL
#define T_M      (2 * ACTPL)                 // 34816
#define T_W      (T_M + 64 * 132 * 4)        // 68608
#define T_TOTAL  (T_W + 2 * 2 * WPL)         // 207872

__global__ __launch_bounds__(256, 1)
void tail_kernel(const float* __restrict__ m_in,
                 const __nv_bfloat16* __restrict__ whi,
                 const __nv_bfloat16* __restrict__ wlo,
                 const float* __restrict__ br1, const float* __restrict__ br2,
                 const float* __restrict__ bfb,
                 const float* __restrict__ x, const float* __restrict__ u,
                 float* __restrict__ out, int n) {
    extern __shared__ __align__(16) char sm[];
    uint32_t smb = smem_u32(sm);
    int tid = threadIdx.x, wid = tid >> 5, lane = tid & 31;
    int row0 = blockIdx.x * 64;
    int warp_m = wid & 3, warp_n = wid >> 2;

    // prefetch W for g=0 (Wr1_0 = mat2), g=1 (Wr2_0 = mat5)
    prefetch_w(smb + T_W, whi + 2 * 16384, wlo + 2 * 16384, tid);
    prefetch_w(smb + T_W + 2 * WPL, whi + 5 * 16384, wlo + 5 * 16384, tid);

    // stage m (fp32) + act = split(ssp(m))
    {
        const float4* M4 = reinterpret_cast<const float4*>(m_in);
#pragma unroll
        for (int it = 0; it < 8; ++it) {
            int idx = tid + it * 256;
            int row = idx >> 5, k4 = idx & 31;
            float4 v = make_float4(0.f, 0.f, 0.f, 0.f);
            if (row0 + row < n) v = M4[(size_t)(row0 + row) * 32 + k4];
            *reinterpret_cast<float4*>(sm + T_M + (row * 132 + k4 * 4) * 4) = v;
            float4 a = ssp4(v);
            u64 hv, lv;
            split4(a, hv, lv);
            uint32_t off = (uint32_t)(row * TLDA + k4 * 4) * 2;
            *reinterpret_cast<u64*>(sm + T_ACT_HI + off) = hv;
            *reinterpret_cast<u64*>(sm + T_ACT_LO + off) = lv;
        }
    }

    for (int g = 0; g < 7; ++g) {
        if (g < 6) CP_WAIT1(); else CP_WAIT0();
        __syncthreads();                   // W visible + prev epilogue done
        int buf = g & 1;
        float d[8][4];
#pragma unroll
        for (int nt = 0; nt < 8; ++nt)
#pragma unroll
            for (int q = 0; q < 4; ++q) d[nt][q] = 0.f;
        uint32_t wb = T_W + buf * 2 * WPL;
        mma_phase(smb, T_ACT_HI, T_ACT_LO, wb, wb + WPL,
                  lane, warp_m, warp_n, d);
        __syncthreads();                   // all reads of act/W done

        if (g + 2 <= 6) {
            int gn = g + 2;
            int mat = (gn == 6) ? 8 : ((gn & 1) ? 5 + (gn >> 1) : 2 + (gn >> 1));
            prefetch_w(smb + T_W + buf * 2 * WPL,
                       whi + (size_t)mat * 16384, wlo + (size_t)mat * 16384,
                       tid);
        }

        if (g == 6) {
            // out = u*x + d + bf
            const float2* bias2 = reinterpret_cast<const float2*>(bfb);
            const float2* x2 = reinterpret_cast<const float2*>(x);
            const float2* u2 = reinterpret_cast<const float2*>(u);
            float2* out2 = reinterpret_cast<float2*>(out);
#pragma unroll
            for (int half = 0; half < 2; ++half) {
                int r = row0 + warp_m * 16 + (lane >> 2) + half * 8;
                if (r >= n) continue;
#pragma unroll
                for (int nt = 0; nt < 8; ++nt) {
                    int c = warp_n * 64 + nt * 8 + (lane & 3) * 2;
                    float2 bb = bias2[c >> 1];
                    float2 xv = x2[(size_t)r * 64 + (c >> 1)];
                    float2 uv = u2[c >> 1];
                    float2 v;
                    v.x = uv.x * xv.x + d[nt][half * 2 + 0] + bb.x;
                    v.y = uv.y * xv.y + d[nt][half * 2 + 1] + bb.y;
                    out2[(size_t)r * 64 + (c >> 1)] = v;
                }
            }
        } else if ((g & 1) == 0) {
            // act = split(ssp(d + br1))
            const float2* bias2 =
                reinterpret_cast<const float2*>(br1 + (g >> 1) * 128);
#pragma unroll
            for (int half = 0; half < 2; ++half) {
                int row = warp_m * 16 + (lane >> 2) + half * 8;
#pragma unroll
                for (int nt = 0; nt < 8; ++nt) {
                    int c = warp_n * 64 + nt * 8 + (lane & 3) * 2;
                    float2 bb = bias2[c >> 1];
                    float sx = ssp(d[nt][half * 2 + 0] + bb.x);
                    float sy = ssp(d[nt][half * 2 + 1] + bb.y);
                    __nv_bfloat162 h = __floats2bfloat162_rn(sx, sy);
                    __nv_bfloat162 l = __floats2bfloat162_rn(
                        sx - __bfloat162float(h.x), sy - __bfloat162float(h.y));
                    uint32_t off = (uint32_t)(row * TLDA + c) * 2;
                    *reinterpret_cast<__nv_bfloat162*>(sm + T_ACT_HI + off) = h;
                    *reinterpret_cast<__nv_bfloat162*>(sm + T_ACT_LO + off) = l;
                }
            }
        } else {
            // m += d + br2; act = split(ssp(m))
            const float2* bias2 =
                reinterpret_cast<const float2*>(br2 + (g >> 1) * 128);
#pragma unroll
            for (int half = 0; half < 2; ++half) {
                int row = warp_m * 16 + (lane >> 2) + half * 8;
#pragma unroll
                for (int nt = 0; nt < 8; ++nt) {
                    int c = warp_n * 64 + nt * 8 + (lane & 3) * 2;
                    float2 bb = bias2[c >> 1];
                    float2* mp = reinterpret_cast<float2*>(
                        sm + T_M + (uint32_t)(row * 132 + c) * 4);
                    float2 mv = *mp;
                    mv.x += d[nt][half * 2 + 0] + bb.x;
                    mv.y += d[nt][half * 2 + 1] + bb.y;
                    *mp = mv;
                    float sx = ssp(mv.x), sy = ssp(mv.y);
                    __nv_bfloat162 h = __floats2bfloat162_rn(sx, sy);
                    __nv_bfloat162 l = __floats2bfloat162_rn(
                        sx - __bfloat162float(h.x), sy - __bfloat162float(h.y));
                    uint32_t off = (uint32_t)(row * TLDA + c) * 2;
                    *reinterpret_cast<__nv_bfloat162*>(sm + T_ACT_HI + off) = h;
                    *reinterpret_cast<__nv_bfloat162*>(sm + T_ACT_LO + off) = l;
                }
            }
        }
    }
}

// ---------------------------------------------------------------------------
// Edge kernel (round-10 pipelined MMA version, unchanged)
// ---------------------------------------------------------------------------
#define ELDK 72
#define EW_PLANE (128 * ELDK * 2)
#define EA_PLANE (64 * ELDK * 2)
#define EG_LD 132
#define ESM_WHI 0
#define ESM_WLO (ESM_WHI + EW_PLANE)
#define ESM_AHI (ESM_WLO + EW_PLANE)
#define ESM_ALO (ESM_AHI + EA_PLANE)
#define ESM_G   (ESM_ALO + EA_PLANE)
#define ESM_TOTAL (ESM_G + 64 * EG_LD * 4)

__global__ __launch_bounds__(256, 2)
void edge_mma(const float* __restrict__ rbf,
              const __nv_bfloat16* __restrict__ wkhi,
              const __nv_bfloat16* __restrict__ wklo,
              const float* __restrict__ xjall, const int* __restrict__ ii,
              const int* __restrict__ jj, float* __restrict__ mout) {
    extern __shared__ __align__(16) char sm[];
    uint32_t smb = smem_u32(sm);
    int tid = threadIdx.x;
    int wid = tid >> 5;
    int lane = tid & 31;

    {
        const uint4* srcH = reinterpret_cast<const uint4*>(wkhi);
        const uint4* srcL = reinterpret_cast<const uint4*>(wklo);
#pragma unroll
        for (int it = 0; it < 4; ++it) {
            int idx = tid + it * 256;
            int row = idx >> 3;
            int seg = idx & 7;
            uint32_t off = (uint32_t)(row * ELDK + seg * 8) * 2;
            *reinterpret_cast<uint4*>(sm + ESM_WHI + off) = srcH[idx];
            *reinterpret_cast<uint4*>(sm + ESM_WLO + off) = srcL[idx];
        }
    }

    int warp_m = wid & 1;
    int warp_n = wid >> 1;
    int a_row = warp_m * 32 + (lane & 15);
    int a_k8 = (lane >> 4) * 8;
    int b_n = warp_n * 32 + (lane >> 4) * 8 + (lane & 7);
    int b_k8 = ((lane >> 3) & 1) * 8;

    int tx = tid & 31;
    int eg = tid >> 5;
    int c0 = tx * 4;
    long base = (long)blockIdx.x * 512;

    const float4* rbf4 = reinterpret_cast<const float4*>(rbf);

    int cur_i = -1;
    float racc[4] = {0.f, 0.f, 0.f, 0.f};

    float4 pre[4];
#pragma unroll
    for (int s = 0; s < 4; ++s) {
        int idx = tid + s * 256;
        long e = base + (idx >> 4);
        pre[s] = (e < E_) ? rbf4[e * 16 + (idx & 15)]
                          : make_float4(0.f, 0.f, 0.f, 0.f);
    }

    for (int t = 0; t < 8; ++t) {
        __syncthreads();
#pragma unroll
        for (int s = 0; s < 4; ++s) {
            int idx = tid + s * 256;
            int er = idx >> 4;
            int k4 = idx & 15;
            u64 hv, lv;
            split4(pre[s], hv, lv);
            uint32_t off = (uint32_t)(er * ELDK + k4 * 4) * 2;
            *reinterpret_cast<u64*>(sm + ESM_AHI + off) = hv;
            *reinterpret_cast<u64*>(sm + ESM_ALO + off) = lv;
        }
        __syncthreads();

        if (t < 7) {
#pragma unroll
            for (int s = 0; s < 4; ++s) {
                int idx = tid + s * 256;
                long e = base + (t + 1) * 64 + (idx >> 4);
                pre[s] = (e < E_) ? rbf4[e * 16 + (idx & 15)]
                                  : make_float4(0.f, 0.f, 0.f, 0.f);
            }
        }

        float d[2][4][4];
#pragma unroll
        for (int mt = 0; mt < 2; ++mt)
#pragma unroll
            for (int nt = 0; nt < 4; ++nt)
#pragma unroll
                for (int q = 0; q < 4; ++q) d[mt][nt][q] = 0.f;

#pragma unroll
        for (int ks = 0; ks < 4; ++ks) {
            int kb = ks * 16;
            unsigned bh[2][4], bl[2][4], ah[2][4], al[2][4];
#pragma unroll
            for (int p = 0; p < 2; ++p) {
                uint32_t boff =
                    (uint32_t)((b_n + p * 16) * ELDK + kb + b_k8) * 2;
                ldsm4(bh[p], smb + ESM_WHI + boff);
                ldsm4(bl[p], smb + ESM_WLO + boff);
            }
#pragma unroll
            for (int mt = 0; mt < 2; ++mt) {
                uint32_t aoff =
                    (uint32_t)((a_row + mt * 16) * ELDK + kb + a_k8) * 2;
                ldsm4(ah[mt], smb + ESM_AHI + aoff);
                ldsm4(al[mt], smb + ESM_ALO + aoff);
            }
#pragma unroll
            for (int term = 0; term < 3; ++term) {
#pragma unroll
                for (int mt = 0; mt < 2; ++mt) {
#pragma unroll
                    for (int nt = 0; nt < 4; ++nt) {
                        const unsigned* af = (term == 2) ? al[mt] : ah[mt];
                        const unsigned* bf =
                            (term == 1) ? bl[nt >> 1] : bh[nt >> 1];
                        mma16816(d[mt][nt], af, bf[(nt & 1) * 2],
                                 bf[(nt & 1) * 2 + 1]);
                    }
                }
            }
        }

#pragma unroll
        for (int mt = 0; mt < 2; ++mt)
#pragma unroll
            for (int half = 0; half < 2; ++half) {
                int row = warp_m * 32 + mt * 16 + (lane >> 2) + half * 8;
#pragma unroll
                for (int nt = 0; nt < 4; ++nt) {
                    int col = warp_n * 32 + nt * 8 + (lane & 3) * 2;
                    float2 v;
                    v.x = d[mt][nt][half * 2 + 0];
                    v.y = d[mt][nt][half * 2 + 1];
                    *reinterpret_cast<float2*>(
                        sm + ESM_G + (uint32_t)(row * EG_LD + col) * 4) = v;
                }
            }
        __syncthreads();

        int iarr[8];
        float4 xv[8];
#pragma unroll
        for (int s = 0; s < 8; ++s) {
            long e = base + t * 64 + eg * 8 + s;
            if (e < E_) {
                iarr[s] = __ldg(ii + e);
                int j = __ldg(jj + e);
                xv[s] = __ldg(reinterpret_cast<const float4*>(
                                  xjall + (size_t)j * 128) + tx);
            } else {
                iarr[s] = -1;
                xv[s] = make_float4(0.f, 0.f, 0.f, 0.f);
            }
        }
#pragma unroll
        for (int s = 0; s < 8; ++s) {
            if (iarr[s] < 0) continue;
            float4 g4 = *reinterpret_cast<const float4*>(
                sm + ESM_G + (uint32_t)((eg * 8 + s) * EG_LD + c0) * 4);
            float v0 = g4.x * xv[s].x;
            float v1 = g4.y * xv[s].y;
            float v2 = g4.z * xv[s].z;
            float v3 = g4.w * xv[s].w;
            if (iarr[s] != cur_i) {
                if (cur_i >= 0) {
                    float* dst = mout + (size_t)cur_i * 128 + c0;
                    atomicAdd(dst + 0, racc[0]);
                    atomicAdd(dst + 1, racc[1]);
                    atomicAdd(dst + 2, racc[2]);
                    atomicAdd(dst + 3, racc[3]);
                }
                cur_i = iarr[s];
                racc[0] = v0; racc[1] = v1; racc[2] = v2; racc[3] = v3;
            } else {
                racc[0] += v0; racc[1] += v1; racc[2] += v2; racc[3] += v3;
            }
        }
    }
    if (cur_i >= 0) {
        float* dst = mout + (size_t)cur_i * 128 + c0;
        atomicAdd(dst + 0, racc[0]);
        atomicAdd(dst + 1, racc[1]);
        atomicAdd(dst + 2, racc[2]);
        atomicAdd(dst + 3, racc[3]);
    }
}

// ---------------------------------------------------------------------------
// Launch
// ---------------------------------------------------------------------------
extern "C" void kernel_launch(void* const* d_in, const int* in_sizes, int n_in,
                              void* d_out, int out_size) {
    const float* x    = (const float*)d_in[0];
    const float* rbf  = (const float*)d_in[1];
    const float* Wk2f = (const float*)d_in[2];
    const float* Wi   = (const float*)d_in[3];
    const float* bi   = (const float*)d_in[4];
    const float* Wj   = (const float*)d_in[5];
    const float* bj   = (const float*)d_in[6];
    const float* Wr1  = (const float*)d_in[7];
    const float* br1  = (const float*)d_in[8];
    const float* Wr2  = (const float*)d_in[9];
    const float* br2  = (const float*)d_in[10];
    const float* Wf   = (const float*)d_in[11];
    const float* bfb  = (const float*)d_in[12];
    const float* u    = (const float*)d_in[13];
    const int* idx_i  = (const int*)d_in[14];
    const int* idx_j  = (const int*)d_in[15];
    float* out = (float*)d_out;

    void *p_m, *p_xjall, *p_hi, *p_lo, *p_wkh, *p_wkl;
    cudaGetSymbolAddress(&p_m, g_m);
    cudaGetSymbolAddress(&p_xjall, g_xjall);
    cudaGetSymbolAddress(&p_hi, g_wthi);
    cudaGetSymbolAddress(&p_lo, g_wtlo);
    cudaGetSymbolAddress(&p_wkh, g_wkhi);
    cudaGetSymbolAddress(&p_wkl, g_wklo);
    float* m = (float*)p_m;
    float* xjall = (float*)p_xjall;
    __nv_bfloat16* whi = (__nv_bfloat16*)p_hi;
    __nv_bfloat16* wlo = (__nv_bfloat16*)p_lo;
    __nv_bfloat16* wkhi = (__nv_bfloat16*)p_wkh;
    __nv_bfloat16* wklo = (__nv_bfloat16*)p_wkl;

    cudaFuncSetAttribute(head_kernel,
                         cudaFuncAttributeMaxDynamicSharedMemorySize, H_TOTAL);
    cudaFuncSetAttribute(tail_kernel,
                         cudaFuncAttributeMaxDynamicSharedMemorySize, T_TOTAL);
    cudaFuncSetAttribute(edge_mma,
                         cudaFuncAttributeMaxDynamicSharedMemorySize, ESM_TOTAL);

    // one-time weight packing
    dim3 pw(64, 9);
    packw_kernel<<<pw, 256>>>(Wi, Wj, Wr1, Wr2, Wf, whi, wlo);
    packwk_kernel<<<32, 256>>>(Wk2f, wkhi, wklo);

    int node_blocks = (N_ + 63) / 64;     // 782
    int edge_blocks = (E_ + 511) / 512;   // 1563

    // m = ssp(ssp(x)@Wi+bi); xjall = ssp(ssp(x)@Wj+bj)
    head_kernel<<<node_blocks, 256, H_TOTAL>>>(x, whi, wlo, bi, bj,
                                               m, xjall, N_);
    // m += segment_sum((rbf@Wk2f) * xjall[idx_j], idx_i)
    edge_mma<<<edge_blocks, 256, ESM_TOTAL>>>(rbf, wkhi, wklo, xjall,
                                              idx_i, idx_j, m);
    // fused residual chain + final projection
    tail_kernel<<<node_blocks, 256, T_TOTAL>>>(m, whi, wlo, br1, br2, bfb,
                                               x, u, out, N_);
}

// round 16
// speedup vs baseline: 1.0016x; 1.0016x over previous
#include <cuda_runtime.h>
#include <cuda_bf16.h>
#include <cstdint>

#define N_ 50000
#define F_ 128
#define E_ 800000
#define K_ 64
#define L_ 3

using u64 = unsigned long long;

// ---------------------------------------------------------------------------
// Scratch (static device globals — no runtime allocation)
// ---------------------------------------------------------------------------
__device__ float g_m[(size_t)N_ * F_];      // xi, then m (edge adds into it)
__device__ float g_xjall[(size_t)N_ * F_];  // ssp(ssp(x)@Wj+bj)
// bf16-split transposed node weights: [mat 0..8][c 0..127][k 0..127]
//   0=Wi 1=Wj 2..4=Wr1[l] 5..7=Wr2[l] 8=Wf
__device__ __nv_bfloat16 g_wthi[9 * 128 * 128];
__device__ __nv_bfloat16 g_wtlo[9 * 128 * 128];
// bf16-split transposed Wk2f: [c 0..127][k 0..63]
__device__ __nv_bfloat16 g_wkhi[128 * 64];
__device__ __nv_bfloat16 g_wklo[128 * 64];

__device__ __forceinline__ float ssp(float v) {
    float ax = fabsf(v);
    return fmaxf(v, 0.0f) + __logf(1.0f + __expf(-ax)) -
           0.69314718055994530942f;
}
__device__ __forceinline__ float4 ssp4(float4 v) {
    v.x = ssp(v.x); v.y = ssp(v.y); v.z = ssp(v.z); v.w = ssp(v.w);
    return v;
}

__device__ __forceinline__ uint32_t smem_u32(const void* p) {
    uint32_t a;
    asm("{ .reg .u64 t; cvta.to.shared.u64 t, %1; cvt.u32.u64 %0, t; }"
        : "=r"(a) : "l"(p));
    return a;
}

__device__ __forceinline__ void ldsm4(unsigned* r, uint32_t addr) {
    asm volatile(
        "ldmatrix.sync.aligned.m8n8.x4.shared.b16 {%0,%1,%2,%3}, [%4];"
        : "=r"(r[0]), "=r"(r[1]), "=r"(r[2]), "=r"(r[3]) : "r"(addr));
}

__device__ __forceinline__ void mma16816(float* d, const unsigned* a,
                                         const unsigned b0, const unsigned b1) {
    asm volatile(
        "mma.sync.aligned.m16n8k16.row.col.f32.bf16.bf16.f32 "
        "{%0,%1,%2,%3}, {%4,%5,%6,%7}, {%8,%9}, {%0,%1,%2,%3};"
        : "+f"(d[0]), "+f"(d[1]), "+f"(d[2]), "+f"(d[3])
        : "r"(a[0]), "r"(a[1]), "r"(a[2]), "r"(a[3]), "r"(b0), "r"(b1));
}

__device__ __forceinline__ void split4(float4 v, u64& hv, u64& lv) {
    __nv_bfloat162 h01 = __floats2bfloat162_rn(v.x, v.y);
    __nv_bfloat162 h23 = __floats2bfloat162_rn(v.z, v.w);
    __nv_bfloat162 l01 = __floats2bfloat162_rn(
        v.x - __bfloat162float(h01.x), v.y - __bfloat162float(h01.y));
    __nv_bfloat162 l23 = __floats2bfloat162_rn(
        v.z - __bfloat162float(h23.x), v.w - __bfloat162float(h23.y));
    hv = ((u64)*reinterpret_cast<uint32_t*>(&h23) << 32) |
         *reinterpret_cast<uint32_t*>(&h01);
    lv = ((u64)*reinterpret_cast<uint32_t*>(&l23) << 32) |
         *reinterpret_cast<uint32_t*>(&l01);
}

// cp.async helpers
__device__ __forceinline__ void cp16(uint32_t dst, const void* src) {
    asm volatile("cp.async.cg.shared.global [%0], [%1], 16;"
                 :: "r"(dst), "l"(src));
}
#define CP_COMMIT() asm volatile("cp.async.commit_group;" ::: "memory")
#define CP_WAIT1() asm volatile("cp.async.wait_group 1;" ::: "memory")
#define CP_WAIT0() asm volatile("cp.async.wait_group 0;" ::: "memory")

// ---------------------------------------------------------------------------
// Weight packing (one-time)
// ---------------------------------------------------------------------------
__global__ void packw_kernel(const float* __restrict__ Wi,
                             const float* __restrict__ Wj,
                             const float* __restrict__ Wr1,
                             const float* __restrict__ Wr2,
                             const float* __restrict__ Wf,
                             __nv_bfloat16* __restrict__ hi,
                             __nv_bfloat16* __restrict__ lo) {
    int m = blockIdx.y;
    const float* W;
    if (m == 0) W = Wi;
    else if (m == 1) W = Wj;
    else if (m < 5) W = Wr1 + (size_t)(m - 2) * F_ * F_;
    else if (m < 8) W = Wr2 + (size_t)(m - 5) * F_ * F_;
    else W = Wf;
    int i = blockIdx.x * blockDim.x + threadIdx.x;
    if (i < 128 * 128) {
        int c = i >> 7, k = i & 127;
        float f = W[k * 128 + c];
        __nv_bfloat16 h = __float2bfloat16_rn(f);
        __nv_bfloat16 l = __float2bfloat16_rn(f - __bfloat162float(h));
        hi[(size_t)m * 16384 + i] = h;
        lo[(size_t)m * 16384 + i] = l;
    }
}

__global__ void packwk_kernel(const float* __restrict__ W,
                              __nv_bfloat16* __restrict__ hi,
                              __nv_bfloat16* __restrict__ lo) {
    int i = blockIdx.x * blockDim.x + threadIdx.x;
    if (i < 128 * 64) {
        int c = i >> 6, k = i & 63;
        float f = W[k * 128 + c];
        __nv_bfloat16 h = __float2bfloat16_rn(f);
        __nv_bfloat16 l = __float2bfloat16_rn(f - __bfloat162float(h));
        hi[i] = h;
        lo[i] = l;
    }
}

// ---------------------------------------------------------------------------
// Shared GEMM core: 64 rows x 128 cols x K=128, 3-term bf16 split.
// 8 warps = 4 row-groups x 2 col-groups; warp = 16 rows x 64 cols
// (1 m16 x 8 n8), d[8][4]. Layouts proven in rounds 6-11.
// ---------------------------------------------------------------------------
#define TLDA 136
#define ACTPL (64 * TLDA * 2)     // 17408 B per act plane
#define WPL   (128 * TLDA * 2)    // 34816 B per W plane

// prefetch one W matrix (hi+lo) into buffer at dsthi (lo at +WPL); 1 group
__device__ __forceinline__ void prefetch_w(uint32_t dsthi,
                                           const __nv_bfloat16* hi,
                                           const __nv_bfloat16* lo, int tid) {
    uint32_t dstlo = dsthi + WPL;
#pragma unroll
    for (int it = 0; it < 8; ++it) {
        int idx = tid + it * 256;       // 0..2047
        int c = idx >> 4, seg = idx & 15;
        uint32_t off = (uint32_t)(c * TLDA + seg * 8) * 2;
        cp16(dsthi + off, hi + idx * 8);
        cp16(dstlo + off, lo + idx * 8);
    }
    CP_COMMIT();
}

__device__ __forceinline__ void mma_phase(uint32_t smb, uint32_t ahoff,
                                          uint32_t aloff, uint32_t whoff,
                                          uint32_t wloff, int lane,
                                          int warp_m, int warp_n,
                                          float d[8][4]) {
    int a_row = warp_m * 16 + (lane & 15);
    int a_k8 = (lane >> 4) * 8;
    int b_n = warp_n * 64 + (lane >> 4) * 8 + (lane & 7);
    int b_k8 = ((lane >> 3) & 1) * 8;
#pragma unroll
    for (int ks = 0; ks < 8; ++ks) {
        int kb = ks * 16;
        unsigned bh[4][4], bl[4][4], ah[4], al[4];
#pragma unroll
        for (int p = 0; p < 4; ++p) {
            uint32_t boff =
                (uint32_t)((b_n + p * 16) * TLDA + kb + b_k8) * 2;
            ldsm4(bh[p], smb + whoff + boff);
            ldsm4(bl[p], smb + wloff + boff);
        }
        uint32_t aoff = (uint32_t)(a_row * TLDA + kb + a_k8) * 2;
        ldsm4(ah, smb + ahoff + aoff);
        ldsm4(al, smb + aloff + aoff);
#pragma unroll
        for (int term = 0; term < 3; ++term) {
#pragma unroll
            for (int nt = 0; nt < 8; ++nt) {
                const unsigned* af = (term == 2) ? al : ah;
                const unsigned* bf = (term == 1) ? bl[nt >> 1] : bh[nt >> 1];
                mma16816(d[nt], af, bf[(nt & 1) * 2], bf[(nt & 1) * 2 + 1]);
            }
        }
    }
}

// ---------------------------------------------------------------------------
// head: per 64-row CTA, stage split(ssp(x)); GEMM Wi -> m, GEMM Wj -> xjall.
// smem: act hi/lo + 2 double-buffered W pairs = 174080 B -> 1 CTA/SM.
// ---------------------------------------------------------------------------
#define H_ACT_HI 0
#define H_ACT_LO ACTPL
#define H_W      (2 * ACTPL)
#define H_TOTAL  (2 * ACTPL + 2 * 2 * WPL)   // 174080

__global__ __launch_bounds__(256, 1)
void head_kernel(const float* __restrict__ x,
                 const __nv_bfloat16* __restrict__ whi,
                 const __nv_bfloat16* __restrict__ wlo,
                 const float* __restrict__ bi, const float* __restrict__ bj,
                 float* __restrict__ m, float* __restrict__ xjall, int n) {
    extern __shared__ __align__(16) char sm[];
    uint32_t smb = smem_u32(sm);
    int tid = threadIdx.x, wid = tid >> 5, lane = tid & 31;
    int row0 = blockIdx.x * 64;
    int warp_m = wid & 3, warp_n = wid >> 2;

    prefetch_w(smb + H_W, whi, wlo, tid);                       // Wi -> buf0
    prefetch_w(smb + H_W + 2 * WPL, whi + 16384, wlo + 16384, tid);  // Wj

    // stage act = split(ssp(x))
    {
        const float4* X4 = reinterpret_cast<const float4*>(x);
#pragma unroll
        for (int it = 0; it < 8; ++it) {
            int idx = tid + it * 256;
            int row = idx >> 5, k4 = idx & 31;
            float4 v = make_float4(0.f, 0.f, 0.f, 0.f);
            if (row0 + row < n) v = X4[(size_t)(row0 + row) * 32 + k4];
            v = ssp4(v);
            u64 hv, lv;
            split4(v, hv, lv);
            uint32_t off = (uint32_t)(row * TLDA + k4 * 4) * 2;
            *reinterpret_cast<u64*>(sm + H_ACT_HI + off) = hv;
            *reinterpret_cast<u64*>(sm + H_ACT_LO + off) = lv;
        }
    }

#pragma unroll
    for (int g = 0; g < 2; ++g) {
        if (g == 0) CP_WAIT1(); else CP_WAIT0();
        __syncthreads();
        float d[8][4];
#pragma unroll
        for (int nt = 0; nt < 8; ++nt)
#pragma unroll
            for (int q = 0; q < 4; ++q) d[nt][q] = 0.f;
        uint32_t wb = H_W + g * 2 * WPL;
        mma_phase(smb, H_ACT_HI, H_ACT_LO, wb, wb + WPL,
                  lane, warp_m, warp_n, d);

        const float* bias = g ? bj : bi;
        float* C = g ? xjall : m;
        const float2* bias2 = reinterpret_cast<const float2*>(bias);
        float2* C2 = reinterpret_cast<float2*>(C);
#pragma unroll
        for (int half = 0; half < 2; ++half) {
            int r = row0 + warp_m * 16 + (lane >> 2) + half * 8;
            if (r >= n) continue;
#pragma unroll
            for (int nt = 0; nt < 8; ++nt) {
                int c = warp_n * 64 + nt * 8 + (lane & 3) * 2;
                float2 bb = bias2[c >> 1];
                float2 v;
                v.x = ssp(d[nt][half * 2 + 0] + bb.x);
                v.y = ssp(d[nt][half * 2 + 1] + bb.y);
                C2[(size_t)r * 64 + (c >> 1)] = v;
            }
        }
        __syncthreads();
    }
}

// ---------------------------------------------------------------------------
// tail: per 64-row CTA, m resident in smem; 7 fused GEMMs
// (Wr1/Wr2 x3, Wf), W streamed 2-deep via cp.async.
// smem: act(2x17408) + m fp32(64x132x4=33792) + 2 W pairs = 207872 B.
// ---------------------------------------------------------------------------
#define T_ACT_HI 0
#define T_ACT_LO ACTPL
#define T_M      (2 * ACTPL)                 // 34816
#define T_W      (T_M + 64 * 132 * 4)        // 68608
#define T_TOTAL  (T_W + 2 * 2 * WPL)         // 207872

__global__ __launch_bounds__(256, 1)
void tail_kernel(const float* __restrict__ m_in,
                 const __nv_bfloat16* __restrict__ whi,
                 const __nv_bfloat16* __restrict__ wlo,
                 const float* __restrict__ br1, const float* __restrict__ br2,
                 const float* __restrict__ bfb,
                 const float* __restrict__ x, const float* __restrict__ u,
                 float* __restrict__ out, int n) {
    extern __shared__ __align__(16) char sm[];
    uint32_t smb = smem_u32(sm);
    int tid = threadIdx.x, wid = tid >> 5, lane = tid & 31;
    int row0 = blockIdx.x * 64;
    int warp_m = wid & 3, warp_n = wid >> 2;

    // prefetch W for g=0 (Wr1_0 = mat2), g=1 (Wr2_0 = mat5)
    prefetch_w(smb + T_W, whi + 2 * 16384, wlo + 2 * 16384, tid);
    prefetch_w(smb + T_W + 2 * WPL, whi + 5 * 16384, wlo + 5 * 16384, tid);

    // stage m (fp32) + act = split(ssp(m))
    {
        const float4* M4 = reinterpret_cast<const float4*>(m_in);
#pragma unroll
        for (int it = 0; it < 8; ++it) {
            int idx = tid + it * 256;
            int row = idx >> 5, k4 = idx & 31;
            float4 v = make_float4(0.f, 0.f, 0.f, 0.f);
            if (row0 + row < n) v = M4[(size_t)(row0 + row) * 32 + k4];
            *reinterpret_cast<float4*>(sm + T_M + (row * 132 + k4 * 4) * 4) = v;
            float4 a = ssp4(v);
            u64 hv, lv;
            split4(a, hv, lv);
            uint32_t off = (uint32_t)(row * TLDA + k4 * 4) * 2;
            *reinterpret_cast<u64*>(sm + T_ACT_HI + off) = hv;
            *reinterpret_cast<u64*>(sm + T_ACT_LO + off) = lv;
        }
    }

    for (int g = 0; g < 7; ++g) {
        if (g < 6) CP_WAIT1(); else CP_WAIT0();
        __syncthreads();                   // W visible + prev epilogue done
        int buf = g & 1;
        float d[8][4];
#pragma unroll
        for (int nt = 0; nt < 8; ++nt)
#pragma unroll
            for (int q = 0; q < 4; ++q) d[nt][q] = 0.f;
        uint32_t wb = T_W + buf * 2 * WPL;
        mma_phase(smb, T_ACT_HI, T_ACT_LO, wb, wb + WPL,
                  lane, warp_m, warp_n, d);
        __syncthreads();                   // all reads of act/W done

        if (g + 2 <= 6) {
            int gn = g + 2;
            int mat = (gn == 6) ? 8 : ((gn & 1) ? 5 + (gn >> 1) : 2 + (gn >> 1));
            prefetch_w(smb + T_W + buf * 2 * WPL,
                       whi + (size_t)mat * 16384, wlo + (size_t)mat * 16384,
                       tid);
        }

        if (g == 6) {
            // out = u*x + d + bf
            const float2* bias2 = reinterpret_cast<const float2*>(bfb);
            const float2* x2 = reinterpret_cast<const float2*>(x);
            const float2* u2 = reinterpret_cast<const float2*>(u);
            float2* out2 = reinterpret_cast<float2*>(out);
#pragma unroll
            for (int half = 0; half < 2; ++half) {
                int r = row0 + warp_m * 16 + (lane >> 2) + half * 8;
                if (r >= n) continue;
#pragma unroll
                for (int nt = 0; nt < 8; ++nt) {
                    int c = warp_n * 64 + nt * 8 + (lane & 3) * 2;
                    float2 bb = bias2[c >> 1];
                    float2 xv = x2[(size_t)r * 64 + (c >> 1)];
                    float2 uv = u2[c >> 1];
                    float2 v;
                    v.x = uv.x * xv.x + d[nt][half * 2 + 0] + bb.x;
                    v.y = uv.y * xv.y + d[nt][half * 2 + 1] + bb.y;
                    out2[(size_t)r * 64 + (c >> 1)] = v;
                }
            }
        } else if ((g & 1) == 0) {
            // act = split(ssp(d + br1))
            const float2* bias2 =
                reinterpret_cast<const float2*>(br1 + (g >> 1) * 128);
#pragma unroll
            for (int half = 0; half < 2; ++half) {
                int row = warp_m * 16 + (lane >> 2) + half * 8;
#pragma unroll
                for (int nt = 0; nt < 8; ++nt) {
                    int c = warp_n * 64 + nt * 8 + (lane & 3) * 2;
                    float2 bb = bias2[c >> 1];
                    float sx = ssp(d[nt][half * 2 + 0] + bb.x);
                    float sy = ssp(d[nt][half * 2 + 1] + bb.y);
                    __nv_bfloat162 h = __floats2bfloat162_rn(sx, sy);
                    __nv_bfloat162 l = __floats2bfloat162_rn(
                        sx - __bfloat162float(h.x), sy - __bfloat162float(h.y));
                    uint32_t off = (uint32_t)(row * TLDA + c) * 2;
                    *reinterpret_cast<__nv_bfloat162*>(sm + T_ACT_HI + off) = h;
                    *reinterpret_cast<__nv_bfloat162*>(sm + T_ACT_LO + off) = l;
                }
            }
        } else {
            // m += d + br2; act = split(ssp(m))
            const float2* bias2 =
                reinterpret_cast<const float2*>(br2 + (g >> 1) * 128);
#pragma unroll
            for (int half = 0; half < 2; ++half) {
                int row = warp_m * 16 + (lane >> 2) + half * 8;
#pragma unroll
                for (int nt = 0; nt < 8; ++nt) {
                    int c = warp_n * 64 + nt * 8 + (lane & 3) * 2;
                    float2 bb = bias2[c >> 1];
                    float2* mp = reinterpret_cast<float2*>(
                        sm + T_M + (uint32_t)(row * 132 + c) * 4);
                    float2 mv = *mp;
                    mv.x += d[nt][half * 2 + 0] + bb.x;
                    mv.y += d[nt][half * 2 + 1] + bb.y;
                    *mp = mv;
                    float sx = ssp(mv.x), sy = ssp(mv.y);
                    __nv_bfloat162 h = __floats2bfloat162_rn(sx, sy);
                    __nv_bfloat162 l = __floats2bfloat162_rn(
                        sx - __bfloat162float(h.x), sy - __bfloat162float(h.y));
                    uint32_t off = (uint32_t)(row * TLDA + c) * 2;
                    *reinterpret_cast<__nv_bfloat162*>(sm + T_ACT_HI + off) = h;
                    *reinterpret_cast<__nv_bfloat162*>(sm + T_ACT_LO + off) = l;
                }
            }
        }
    }
}

// ---------------------------------------------------------------------------
// Edge kernel (round-10 pipelined MMA version, unchanged)
// ---------------------------------------------------------------------------
#define ELDK 72
#define EW_PLANE (128 * ELDK * 2)
#define EA_PLANE (64 * ELDK * 2)
#define EG_LD 132
#define ESM_WHI 0
#define ESM_WLO (ESM_WHI + EW_PLANE)
#define ESM_AHI (ESM_WLO + EW_PLANE)
#define ESM_ALO (ESM_AHI + EA_PLANE)
#define ESM_G   (ESM_ALO + EA_PLANE)
#define ESM_TOTAL (ESM_G + 64 * EG_LD * 4)

__global__ __launch_bounds__(256, 2)
void edge_mma(const float* __restrict__ rbf,
              const __nv_bfloat16* __restrict__ wkhi,
              const __nv_bfloat16* __restrict__ wklo,
              const float* __restrict__ xjall, const int* __restrict__ ii,
              const int* __restrict__ jj, float* __restrict__ mout) {
    extern __shared__ __align__(16) char sm[];
    uint32_t smb = smem_u32(sm);
    int tid = threadIdx.x;
    int wid = tid >> 5;
    int lane = tid & 31;

    {
        const uint4* srcH = reinterpret_cast<const uint4*>(wkhi);
        const uint4* srcL = reinterpret_cast<const uint4*>(wklo);
#pragma unroll
        for (int it = 0; it < 4; ++it) {
            int idx = tid + it * 256;
            int row = idx >> 3;
            int seg = idx & 7;
            uint32_t off = (uint32_t)(row * ELDK + seg * 8) * 2;
            *reinterpret_cast<uint4*>(sm + ESM_WHI + off) = srcH[idx];
            *reinterpret_cast<uint4*>(sm + ESM_WLO + off) = srcL[idx];
        }
    }

    int warp_m = wid & 1;
    int warp_n = wid >> 1;
    int a_row = warp_m * 32 + (lane & 15);
    int a_k8 = (lane >> 4) * 8;
    int b_n = warp_n * 32 + (lane >> 4) * 8 + (lane & 7);
    int b_k8 = ((lane >> 3) & 1) * 8;

    int tx = tid & 31;
    int eg = tid >> 5;
    int c0 = tx * 4;
    long base = (long)blockIdx.x * 512;

    const float4* rbf4 = reinterpret_cast<const float4*>(rbf);

    int cur_i = -1;
    float racc[4] = {0.f, 0.f, 0.f, 0.f};

    float4 pre[4];
#pragma unroll
    for (int s = 0; s < 4; ++s) {
        int idx = tid + s * 256;
        long e = base + (idx >> 4);
        pre[s] = (e < E_) ? rbf4[e * 16 + (idx & 15)]
                          : make_float4(0.f, 0.f, 0.f, 0.f);
    }

    for (int t = 0; t < 8; ++t) {
        __syncthreads();
#pragma unroll
        for (int s = 0; s < 4; ++s) {
            int idx = tid + s * 256;
            int er = idx >> 4;
            int k4 = idx & 15;
            u64 hv, lv;
            split4(pre[s], hv, lv);
            uint32_t off = (uint32_t)(er * ELDK + k4 * 4) * 2;
            *reinterpret_cast<u64*>(sm + ESM_AHI + off) = hv;
            *reinterpret_cast<u64*>(sm + ESM_ALO + off) = lv;
        }
        __syncthreads();

        if (t < 7) {
#pragma unroll
            for (int s = 0; s < 4; ++s) {
                int idx = tid + s * 256;
                long e = base + (t + 1) * 64 + (idx >> 4);
                pre[s] = (e < E_) ? rbf4[e * 16 + (idx & 15)]
                                  : make_float4(0.f, 0.f, 0.f, 0.f);
            }
        }

        float d[2][4][4];
#pragma unroll
        for (int mt = 0; mt < 2; ++mt)
#pragma unroll
            for (int nt = 0; nt < 4; ++nt)
#pragma unroll
                for (int q = 0; q < 4; ++q) d[mt][nt][q] = 0.f;

#pragma unroll
        for (int ks = 0; ks < 4; ++ks) {
            int kb = ks * 16;
            unsigned bh[2][4], bl[2][4], ah[2][4], al[2][4];
#pragma unroll
            for (int p = 0; p < 2; ++p) {
                uint32_t boff =
                    (uint32_t)((b_n + p * 16) * ELDK + kb + b_k8) * 2;
                ldsm4(bh[p], smb + ESM_WHI + boff);
                ldsm4(bl[p], smb + ESM_WLO + boff);
            }
#pragma unroll
            for (int mt = 0; mt < 2; ++mt) {
                uint32_t aoff =
                    (uint32_t)((a_row + mt * 16) * ELDK + kb + a_k8) * 2;
                ldsm4(ah[mt], smb + ESM_AHI + aoff);
                ldsm4(al[mt], smb + ESM_ALO + aoff);
            }
#pragma unroll
            for (int term = 0; term < 3; ++term) {
#pragma unroll
                for (int mt = 0; mt < 2; ++mt) {
#pragma unroll
                    for (int nt = 0; nt < 4; ++nt) {
                        const unsigned* af = (term == 2) ? al[mt] : ah[mt];
                        const unsigned* bf =
                            (term == 1) ? bl[nt >> 1] : bh[nt >> 1];
                        mma16816(d[mt][nt], af, bf[(nt & 1) * 2],
                                 bf[(nt & 1) * 2 + 1]);
                    }
                }
            }
        }

#pragma unroll
        for (int mt = 0; mt < 2; ++mt)
#pragma unroll
            for (int half = 0; half < 2; ++half) {
                int row = warp_m * 32 + mt * 16 + (lane >> 2) + half * 8;
#pragma unroll
                for (int nt = 0; nt < 4; ++nt) {
                    int col = warp_n * 32 + nt * 8 + (lane & 3) * 2;
                    float2 v;
                    v.x = d[mt][nt][half * 2 + 0];
                    v.y = d[mt][nt][half * 2 + 1];
                    *reinterpret_cast<float2*>(
                        sm + ESM_G + (uint32_t)(row * EG_LD + col) * 4) = v;
                }
            }
        __syncthreads();

        int iarr[8];
        float4 xv[8];
#pragma unroll
        for (int s = 0; s < 8; ++s) {
            long e = base + t * 64 + eg * 8 + s;
            if (e < E_) {
                iarr[s] = __ldg(ii + e);
                int j = __ldg(jj + e);
                xv[s] = __ldg(reinterpret_cast<const float4*>(
                                  xjall + (size_t)j * 128) + tx);
            } else {
                iarr[s] = -1;
                xv[s] = make_float4(0.f, 0.f, 0.f, 0.f);
            }
        }
#pragma unroll
        for (int s = 0; s < 8; ++s) {
            if (iarr[s] < 0) continue;
            float4 g4 = *reinterpret_cast<const float4*>(
                sm + ESM_G + (uint32_t)((eg * 8 + s) * EG_LD + c0) * 4);
            float v0 = g4.x * xv[s].x;
            float v1 = g4.y * xv[s].y;
            float v2 = g4.z * xv[s].z;
            float v3 = g4.w * xv[s].w;
            if (iarr[s] != cur_i) {
                if (cur_i >= 0) {
                    float* dst = mout + (size_t)cur_i * 128 + c0;
                    atomicAdd(dst + 0, racc[0]);
                    atomicAdd(dst + 1, racc[1]);
                    atomicAdd(dst + 2, racc[2]);
                    atomicAdd(dst + 3, racc[3]);
                }
                cur_i = iarr[s];
                racc[0] = v0; racc[1] = v1; racc[2] = v2; racc[3] = v3;
            } else {
                racc[0] += v0; racc[1] += v1; racc[2] += v2; racc[3] += v3;
            }
        }
    }
    if (cur_i >= 0) {
        float* dst = mout + (size_t)cur_i * 128 + c0;
        atomicAdd(dst + 0, racc[0]);
        atomicAdd(dst + 1, racc[1]);
        atomicAdd(dst + 2, racc[2]);
        atomicAdd(dst + 3, racc[3]);
    }
}

// ---------------------------------------------------------------------------
// Launch
// ---------------------------------------------------------------------------
extern "C" void kernel_launch(void* const* d_in, const int* in_sizes, int n_in,
                              void* d_out, int out_size) {
    const float* x    = (const float*)d_in[0];
    const float* rbf  = (const float*)d_in[1];
    const float* Wk2f = (const float*)d_in[2];
    const float* Wi   = (const float*)d_in[3];
    const float* bi   = (const float*)d_in[4];
    const float* Wj   = (const float*)d_in[5];
    const float* bj   = (const float*)d_in[6];
    const float* Wr1  = (const float*)d_in[7];
    const float* br1  = (const float*)d_in[8];
    const float* Wr2  = (const float*)d_in[9];
    const float* br2  = (const float*)d_in[10];
    const float* Wf   = (const float*)d_in[11];
    const float* bfb  = (const float*)d_in[12];
    const float* u    = (const float*)d_in[13];
    const int* idx_i  = (const int*)d_in[14];
    const int* idx_j  = (const int*)d_in[15];
    float* out = (float*)d_out;

    void *p_m, *p_xjall, *p_hi, *p_lo, *p_wkh, *p_wkl;
    cudaGetSymbolAddress(&p_m, g_m);
    cudaGetSymbolAddress(&p_xjall, g_xjall);
    cudaGetSymbolAddress(&p_hi, g_wthi);
    cudaGetSymbolAddress(&p_lo, g_wtlo);
    cudaGetSymbolAddress(&p_wkh, g_wkhi);
    cudaGetSymbolAddress(&p_wkl, g_wklo);
    float* m = (float*)p_m;
    float* xjall = (float*)p_xjall;
    __nv_bfloat16* whi = (__nv_bfloat16*)p_hi;
    __nv_bfloat16* wlo = (__nv_bfloat16*)p_lo;
    __nv_bfloat16* wkhi = (__nv_bfloat16*)p_wkh;
    __nv_bfloat16* wklo = (__nv_bfloat16*)p_wkl;

    cudaFuncSetAttribute(head_kernel,
                         cudaFuncAttributeMaxDynamicSharedMemorySize, H_TOTAL);
    cudaFuncSetAttribute(tail_kernel,
                         cudaFuncAttributeMaxDynamicSharedMemorySize, T_TOTAL);
    cudaFuncSetAttribute(edge_mma,
                         cudaFuncAttributeMaxDynamicSharedMemorySize, ESM_TOTAL);

    // one-time weight packing
    dim3 pw(64, 9);
    packw_kernel<<<pw, 256>>>(Wi, Wj, Wr1, Wr2, Wf, whi, wlo);
    packwk_kernel<<<32, 256>>>(Wk2f, wkhi, wklo);

    int node_blocks = (N_ + 63) / 64;     // 782
    int edge_blocks = (E_ + 511) / 512;   // 1563

    // m = ssp(ssp(x)@Wi+bi); xjall = ssp(ssp(x)@Wj+bj)
    head_kernel<<<node_blocks, 256, H_TOTAL>>>(x, whi, wlo, bi, bj,
                                               m, xjall, N_);
    // m += segment_sum((rbf@Wk2f) * xjall[idx_j], idx_i)
    edge_mma<<<edge_blocks, 256, ESM_TOTAL>>>(rbf, wkhi, wklo, xjall,
                                              idx_i, idx_j, m);
    // fused residual chain + final projection
    tail_kernel<<<node_blocks, 256, T_TOTAL>>>(m, whi, wlo, br1, br2, bfb,
                                               x, u, out, N_);
}

// round 17
// speedup vs baseline: 1.0617x; 1.0600x over previous
#include <cuda_runtime.h>
#include <cuda_bf16.h>
#include <cstdint>

#define N_ 50000
#define F_ 128
#define E_ 800000
#define K_ 64
#define L_ 3

using u64 = unsigned long long;

// ---------------------------------------------------------------------------
// Scratch (static device globals — no runtime allocation)
// ---------------------------------------------------------------------------
__device__ float g_m[(size_t)N_ * F_];      // xi, then m (edge adds into it)
__device__ float g_xjall[(size_t)N_ * F_];  // ssp(ssp(x)@Wj+bj)
// bf16-split transposed node weights: [mat 0..8][c 0..127][k 0..127]
//   0=Wi 1=Wj 2..4=Wr1[l] 5..7=Wr2[l] 8=Wf
__device__ __nv_bfloat16 g_wthi[9 * 128 * 128];
__device__ __nv_bfloat16 g_wtlo[9 * 128 * 128];
// bf16-split transposed Wk2f: [c 0..127][k 0..63]
__device__ __nv_bfloat16 g_wkhi[128 * 64];
__device__ __nv_bfloat16 g_wklo[128 * 64];

__device__ __forceinline__ float ssp(float v) {
    float ax = fabsf(v);
    return fmaxf(v, 0.0f) + __logf(1.0f + __expf(-ax)) -
           0.69314718055994530942f;
}
__device__ __forceinline__ float4 ssp4(float4 v) {
    v.x = ssp(v.x); v.y = ssp(v.y); v.z = ssp(v.z); v.w = ssp(v.w);
    return v;
}

__device__ __forceinline__ uint32_t smem_u32(const void* p) {
    uint32_t a;
    asm("{ .reg .u64 t; cvta.to.shared.u64 t, %1; cvt.u32.u64 %0, t; }"
        : "=r"(a) : "l"(p));
    return a;
}

__device__ __forceinline__ void ldsm4(unsigned* r, uint32_t addr) {
    asm volatile(
        "ldmatrix.sync.aligned.m8n8.x4.shared.b16 {%0,%1,%2,%3}, [%4];"
        : "=r"(r[0]), "=r"(r[1]), "=r"(r[2]), "=r"(r[3]) : "r"(addr));
}

__device__ __forceinline__ void mma16816(float* d, const unsigned* a,
                                         const unsigned b0, const unsigned b1) {
    asm volatile(
        "mma.sync.aligned.m16n8k16.row.col.f32.bf16.bf16.f32 "
        "{%0,%1,%2,%3}, {%4,%5,%6,%7}, {%8,%9}, {%0,%1,%2,%3};"
        : "+f"(d[0]), "+f"(d[1]), "+f"(d[2]), "+f"(d[3])
        : "r"(a[0]), "r"(a[1]), "r"(a[2]), "r"(a[3]), "r"(b0), "r"(b1));
}

__device__ __forceinline__ void split4(float4 v, u64& hv, u64& lv) {
    __nv_bfloat162 h01 = __floats2bfloat162_rn(v.x, v.y);
    __nv_bfloat162 h23 = __floats2bfloat162_rn(v.z, v.w);
    __nv_bfloat162 l01 = __floats2bfloat162_rn(
        v.x - __bfloat162float(h01.x), v.y - __bfloat162float(h01.y));
    __nv_bfloat162 l23 = __floats2bfloat162_rn(
        v.z - __bfloat162float(h23.x), v.w - __bfloat162float(h23.y));
    hv = ((u64)*reinterpret_cast<uint32_t*>(&h23) << 32) |
         *reinterpret_cast<uint32_t*>(&h01);
    lv = ((u64)*reinterpret_cast<uint32_t*>(&l23) << 32) |
         *reinterpret_cast<uint32_t*>(&l01);
}

// cp.async helpers
__device__ __forceinline__ void cp16(uint32_t dst, const void* src) {
    asm volatile("cp.async.cg.shared.global [%0], [%1], 16;"
                 :: "r"(dst), "l"(src));
}
#define CP_COMMIT() asm volatile("cp.async.commit_group;" ::: "memory")
#define CP_WAIT0() asm volatile("cp.async.wait_group 0;" ::: "memory")

// ---------------------------------------------------------------------------
// Weight packing (one-time)
// ---------------------------------------------------------------------------
__global__ void packw_kernel(const float* __restrict__ Wi,
                             const float* __restrict__ Wj,
                             const float* __restrict__ Wr1,
                             const float* __restrict__ Wr2,
                             const float* __restrict__ Wf,
                             __nv_bfloat16* __restrict__ hi,
                             __nv_bfloat16* __restrict__ lo) {
    int m = blockIdx.y;
    const float* W;
    if (m == 0) W = Wi;
    else if (m == 1) W = Wj;
    else if (m < 5) W = Wr1 + (size_t)(m - 2) * F_ * F_;
    else if (m < 8) W = Wr2 + (size_t)(m - 5) * F_ * F_;
    else W = Wf;
    int i = blockIdx.x * blockDim.x + threadIdx.x;
    if (i < 128 * 128) {
        int c = i >> 7, k = i & 127;
        float f = W[k * 128 + c];
        __nv_bfloat16 h = __float2bfloat16_rn(f);
        __nv_bfloat16 l = __float2bfloat16_rn(f - __bfloat162float(h));
        hi[(size_t)m * 16384 + i] = h;
        lo[(size_t)m * 16384 + i] = l;
    }
}

__global__ void packwk_kernel(const float* __restrict__ W,
                              __nv_bfloat16* __restrict__ hi,
                              __nv_bfloat16* __restrict__ lo) {
    int i = blockIdx.x * blockDim.x + threadIdx.x;
    if (i < 128 * 64) {
        int c = i >> 6, k = i & 63;
        float f = W[k * 128 + c];
        __nv_bfloat16 h = __float2bfloat16_rn(f);
        __nv_bfloat16 l = __float2bfloat16_rn(f - __bfloat162float(h));
        hi[i] = h;
        lo[i] = l;
    }
}

// ---------------------------------------------------------------------------
// Node GEMM core: 64 rows x 128 cols x K=128, 3-term bf16 split.
// 8 warps in 2x4 grid: warp = 32 rows x 32 cols (2 m16 x 4 n8) —
// 8 LDSM per ks per warp (minimum). Layout proven in round 8.
// ---------------------------------------------------------------------------
#define TLDA 136
#define ACTPL (64 * TLDA * 2)     // 17408 B per act plane
#define WPL   (128 * TLDA * 2)    // 34816 B per W plane

// prefetch one W matrix (hi+lo) into single buffer; 1 cp.async group
__device__ __forceinline__ void prefetch_w(uint32_t dsthi,
                                           const __nv_bfloat16* hi,
                                           const __nv_bfloat16* lo, int tid) {
    uint32_t dstlo = dsthi + WPL;
#pragma unroll
    for (int it = 0; it < 8; ++it) {
        int idx = tid + it * 256;       // 0..2047
        int c = idx >> 4, seg = idx & 15;
        uint32_t off = (uint32_t)(c * TLDA + seg * 8) * 2;
        cp16(dsthi + off, hi + idx * 8);
        cp16(dstlo + off, lo + idx * 8);
    }
    CP_COMMIT();
}

__device__ __forceinline__ void mma_phase232(uint32_t smb, uint32_t ahoff,
                                             uint32_t aloff, uint32_t whoff,
                                             uint32_t wloff, int lane,
                                             int warp_m, int warp_n,
                                             float d[2][4][4]) {
    int a_row = warp_m * 32 + (lane & 15);
    int a_k8 = (lane >> 4) * 8;
    int b_n = warp_n * 32 + (lane >> 4) * 8 + (lane & 7);
    int b_k8 = ((lane >> 3) & 1) * 8;
#pragma unroll
    for (int ks = 0; ks < 8; ++ks) {
        int kb = ks * 16;
        unsigned bh[2][4], bl[2][4], ah[2][4], al[2][4];
#pragma unroll
        for (int p = 0; p < 2; ++p) {
            uint32_t boff = (uint32_t)((b_n + p * 16) * TLDA + kb + b_k8) * 2;
            ldsm4(bh[p], smb + whoff + boff);
            ldsm4(bl[p], smb + wloff + boff);
        }
#pragma unroll
        for (int mt = 0; mt < 2; ++mt) {
            uint32_t aoff =
                (uint32_t)((a_row + mt * 16) * TLDA + kb + a_k8) * 2;
            ldsm4(ah[mt], smb + ahoff + aoff);
            ldsm4(al[mt], smb + aloff + aoff);
        }
#pragma unroll
        for (int term = 0; term < 3; ++term) {
#pragma unroll
            for (int mt = 0; mt < 2; ++mt) {
#pragma unroll
                for (int nt = 0; nt < 4; ++nt) {
                    const unsigned* af = (term == 2) ? al[mt] : ah[mt];
                    const unsigned* bf = (term == 1) ? bl[nt >> 1] : bh[nt >> 1];
                    mma16816(d[mt][nt], af, bf[(nt & 1) * 2],
                             bf[(nt & 1) * 2 + 1]);
                }
            }
        }
    }
}

// smem layout shared by head and tail: act hi/lo + ONE W pair
#define SM_ACT_HI 0
#define SM_ACT_LO ACTPL
#define SM_W      (2 * ACTPL)
#define SM_TOTAL  (2 * ACTPL + 2 * WPL)   // 104448 B -> 2 CTAs/SM

// ---------------------------------------------------------------------------
// head: stage split(ssp(x)); GEMM Wi -> m, GEMM Wj -> xjall (both ssp'd).
// ---------------------------------------------------------------------------
__global__ __launch_bounds__(256, 2)
void head_kernel(const float* __restrict__ x,
                 const __nv_bfloat16* __restrict__ whi,
                 const __nv_bfloat16* __restrict__ wlo,
                 const float* __restrict__ bi, const float* __restrict__ bj,
                 float* __restrict__ m, float* __restrict__ xjall, int n) {
    extern __shared__ __align__(16) char sm[];
    uint32_t smb = smem_u32(sm);
    int tid = threadIdx.x, wid = tid >> 5, lane = tid & 31;
    int row0 = blockIdx.x * 64;
    int warp_m = wid & 1, warp_n = wid >> 1;

    prefetch_w(smb + SM_W, whi, wlo, tid);    // Wi

    // stage act = split(ssp(x))
    {
        const float4* X4 = reinterpret_cast<const float4*>(x);
#pragma unroll
        for (int it = 0; it < 8; ++it) {
            int idx = tid + it * 256;
            int row = idx >> 5, k4 = idx & 31;
            float4 v = make_float4(0.f, 0.f, 0.f, 0.f);
            if (row0 + row < n) v = X4[(size_t)(row0 + row) * 32 + k4];
            v = ssp4(v);
            u64 hv, lv;
            split4(v, hv, lv);
            uint32_t off = (uint32_t)(row * TLDA + k4 * 4) * 2;
            *reinterpret_cast<u64*>(sm + SM_ACT_HI + off) = hv;
            *reinterpret_cast<u64*>(sm + SM_ACT_LO + off) = lv;
        }
    }

#pragma unroll
    for (int g = 0; g < 2; ++g) {
        CP_WAIT0();
        __syncthreads();
        float d[2][4][4];
#pragma unroll
        for (int mt = 0; mt < 2; ++mt)
#pragma unroll
            for (int nt = 0; nt < 4; ++nt)
#pragma unroll
                for (int q = 0; q < 4; ++q) d[mt][nt][q] = 0.f;
        mma_phase232(smb, SM_ACT_HI, SM_ACT_LO, SM_W, SM_W + WPL,
                     lane, warp_m, warp_n, d);
        __syncthreads();                       // all W reads done
        if (g == 0) prefetch_w(smb + SM_W, whi + 16384, wlo + 16384, tid);

        const float* bias = g ? bj : bi;
        float* C = g ? xjall : m;
        const float2* bias2 = reinterpret_cast<const float2*>(bias);
        float2* C2 = reinterpret_cast<float2*>(C);
#pragma unroll
        for (int mt = 0; mt < 2; ++mt) {
#pragma unroll
            for (int half = 0; half < 2; ++half) {
                int r = row0 + warp_m * 32 + mt * 16 + (lane >> 2) + half * 8;
                if (r >= n) continue;
#pragma unroll
                for (int nt = 0; nt < 4; ++nt) {
                    int c = warp_n * 32 + nt * 8 + (lane & 3) * 2;
                    float2 bb = bias2[c >> 1];
                    float2 v;
                    v.x = ssp(d[mt][nt][half * 2 + 0] + bb.x);
                    v.y = ssp(d[mt][nt][half * 2 + 1] + bb.y);
                    C2[(size_t)r * 64 + (c >> 1)] = v;
                }
            }
        }
    }
}

// ---------------------------------------------------------------------------
// tail: 7 fused GEMMs (Wr1/Wr2 x3, Wf); act resident in smem, m in GLOBAL
// (each (r,c) owned by the same thread in every phase -> no hazards).
// Single-buffered W; with 2 CTAs/SM the W load overlaps the peer's MMA.
// ---------------------------------------------------------------------------
__global__ __launch_bounds__(256, 2)
void tail_kernel(float* __restrict__ mg,
                 const __nv_bfloat16* __restrict__ whi,
                 const __nv_bfloat16* __restrict__ wlo,
                 const float* __restrict__ br1, const float* __restrict__ br2,
                 const float* __restrict__ bfb,
                 const float* __restrict__ x, const float* __restrict__ u,
                 float* __restrict__ out, int n) {
    extern __shared__ __align__(16) char sm[];
    uint32_t smb = smem_u32(sm);
    int tid = threadIdx.x, wid = tid >> 5, lane = tid & 31;
    int row0 = blockIdx.x * 64;
    int warp_m = wid & 1, warp_n = wid >> 1;

    prefetch_w(smb + SM_W, whi + 2 * 16384, wlo + 2 * 16384, tid);  // Wr1_0

    // stage act = split(ssp(m))
    {
        const float4* M4 = reinterpret_cast<const float4*>(mg);
#pragma unroll
        for (int it = 0; it < 8; ++it) {
            int idx = tid + it * 256;
            int row = idx >> 5, k4 = idx & 31;
            float4 v = make_float4(0.f, 0.f, 0.f, 0.f);
            if (row0 + row < n) v = M4[(size_t)(row0 + row) * 32 + k4];
            float4 a = ssp4(v);
            u64 hv, lv;
            split4(a, hv, lv);
            uint32_t off = (uint32_t)(row * TLDA + k4 * 4) * 2;
            *reinterpret_cast<u64*>(sm + SM_ACT_HI + off) = hv;
            *reinterpret_cast<u64*>(sm + SM_ACT_LO + off) = lv;
        }
    }

    for (int g = 0; g < 7; ++g) {
        CP_WAIT0();
        __syncthreads();                   // W visible; act writes visible
        float d[2][4][4];
#pragma unroll
        for (int mt = 0; mt < 2; ++mt)
#pragma unroll
            for (int nt = 0; nt < 4; ++nt)
#pragma unroll
                for (int q = 0; q < 4; ++q) d[mt][nt][q] = 0.f;
        mma_phase232(smb, SM_ACT_HI, SM_ACT_LO, SM_W, SM_W + WPL,
                     lane, warp_m, warp_n, d);
        __syncthreads();                   // all W/act reads done
        if (g < 6) {
            int gn = g + 1;
            int mat = (gn == 6) ? 8 : ((gn & 1) ? 5 + (gn >> 1) : 2 + (gn >> 1));
            prefetch_w(smb + SM_W, whi + (size_t)mat * 16384,
                       wlo + (size_t)mat * 16384, tid);
        }

        if (g == 6) {
            // out = u*x + d + bf
            const float2* bias2 = reinterpret_cast<const float2*>(bfb);
            const float2* x2 = reinterpret_cast<const float2*>(x);
            const float2* u2 = reinterpret_cast<const float2*>(u);
            float2* out2 = reinterpret_cast<float2*>(out);
#pragma unroll
            for (int mt = 0; mt < 2; ++mt) {
#pragma unroll
                for (int half = 0; half < 2; ++half) {
                    int r = row0 + warp_m * 32 + mt * 16 + (lane >> 2) +
                            half * 8;
                    if (r >= n) continue;
#pragma unroll
                    for (int nt = 0; nt < 4; ++nt) {
                        int c = warp_n * 32 + nt * 8 + (lane & 3) * 2;
                        float2 bb = bias2[c >> 1];
                        float2 xv = x2[(size_t)r * 64 + (c >> 1)];
                        float2 uv = u2[c >> 1];
                        float2 v;
                        v.x = uv.x * xv.x + d[mt][nt][half * 2 + 0] + bb.x;
                        v.y = uv.y * xv.y + d[mt][nt][half * 2 + 1] + bb.y;
                        out2[(size_t)r * 64 + (c >> 1)] = v;
                    }
                }
            }
        } else if ((g & 1) == 0) {
            // act = split(ssp(d + br1))
            const float2* bias2 =
                reinterpret_cast<const float2*>(br1 + (g >> 1) * 128);
#pragma unroll
            for (int mt = 0; mt < 2; ++mt) {
#pragma unroll
                for (int half = 0; half < 2; ++half) {
                    int row = warp_m * 32 + mt * 16 + (lane >> 2) + half * 8;
#pragma unroll
                    for (int nt = 0; nt < 4; ++nt) {
                        int c = warp_n * 32 + nt * 8 + (lane & 3) * 2;
                        float2 bb = bias2[c >> 1];
                        float sx = ssp(d[mt][nt][half * 2 + 0] + bb.x);
                        float sy = ssp(d[mt][nt][half * 2 + 1] + bb.y);
                        __nv_bfloat162 h = __floats2bfloat162_rn(sx, sy);
                        __nv_bfloat162 l = __floats2bfloat162_rn(
                            sx - __bfloat162float(h.x),
                            sy - __bfloat162float(h.y));
                        uint32_t off = (uint32_t)(row * TLDA + c) * 2;
                        *reinterpret_cast<__nv_bfloat162*>(
                            sm + SM_ACT_HI + off) = h;
                        *reinterpret_cast<__nv_bfloat162*>(
                            sm + SM_ACT_LO + off) = l;
                    }
                }
            }
        } else {
            // m += d + br2 (global, thread-owned); act = split(ssp(m))
            const float2* bias2 =
                reinterpret_cast<const float2*>(br2 + (g >> 1) * 128);
            float2* m2 = reinterpret_cast<float2*>(mg);
#pragma unroll
            for (int mt = 0; mt < 2; ++mt) {
#pragma unroll
                for (int half = 0; half < 2; ++half) {
                    int r = row0 + warp_m * 32 + mt * 16 + (lane >> 2) +
                            half * 8;
                    if (r >= n) continue;
                    int row = r - row0;
#pragma unroll
                    for (int nt = 0; nt < 4; ++nt) {
                        int c = warp_n * 32 + nt * 8 + (lane & 3) * 2;
                        float2 bb = bias2[c >> 1];
                        size_t gi = (size_t)r * 64 + (c >> 1);
                        float2 mv = m2[gi];
                        mv.x += d[mt][nt][half * 2 + 0] + bb.x;
                        mv.y += d[mt][nt][half * 2 + 1] + bb.y;
                        m2[gi] = mv;
                        float sx = ssp(mv.x), sy = ssp(mv.y);
                        __nv_bfloat162 h = __floats2bfloat162_rn(sx, sy);
                        __nv_bfloat162 l = __floats2bfloat162_rn(
                            sx - __bfloat162float(h.x),
                            sy - __bfloat162float(h.y));
                        uint32_t off = (uint32_t)(row * TLDA + c) * 2;
                        *reinterpret_cast<__nv_bfloat162*>(
                            sm + SM_ACT_HI + off) = h;
                        *reinterpret_cast<__nv_bfloat162*>(
                            sm + SM_ACT_LO + off) = l;
                    }
                }
            }
        }
    }
}

// ---------------------------------------------------------------------------
// Edge kernel (round-10 pipelined MMA version, unchanged)
// ---------------------------------------------------------------------------
#define ELDK 72
#define EW_PLANE (128 * ELDK * 2)
#define EA_PLANE (64 * ELDK * 2)
#define EG_LD 132
#define ESM_WHI 0
#define ESM_WLO (ESM_WHI + EW_PLANE)
#define ESM_AHI (ESM_WLO + EW_PLANE)
#define ESM_ALO (ESM_AHI + EA_PLANE)
#define ESM_G   (ESM_ALO + EA_PLANE)
#define ESM_TOTAL (ESM_G + 64 * EG_LD * 4)

__global__ __launch_bounds__(256, 2)
void edge_mma(const float* __restrict__ rbf,
              const __nv_bfloat16* __restrict__ wkhi,
              const __nv_bfloat16* __restrict__ wklo,
              const float* __restrict__ xjall, const int* __restrict__ ii,
              const int* __restrict__ jj, float* __restrict__ mout) {
    extern __shared__ __align__(16) char sm[];
    uint32_t smb = smem_u32(sm);
    int tid = threadIdx.x;
    int wid = tid >> 5;
    int lane = tid & 31;

    {
        const uint4* srcH = reinterpret_cast<const uint4*>(wkhi);
        const uint4* srcL = reinterpret_cast<const uint4*>(wklo);
#pragma unroll
        for (int it = 0; it < 4; ++it) {
            int idx = tid + it * 256;
            int row = idx >> 3;
            int seg = idx & 7;
            uint32_t off = (uint32_t)(row * ELDK + seg * 8) * 2;
            *reinterpret_cast<uint4*>(sm + ESM_WHI + off) = srcH[idx];
            *reinterpret_cast<uint4*>(sm + ESM_WLO + off) = srcL[idx];
        }
    }

    int warp_m = wid & 1;
    int warp_n = wid >> 1;
    int a_row = warp_m * 32 + (lane & 15);
    int a_k8 = (lane >> 4) * 8;
    int b_n = warp_n * 32 + (lane >> 4) * 8 + (lane & 7);
    int b_k8 = ((lane >> 3) & 1) * 8;

    int tx = tid & 31;
    int eg = tid >> 5;
    int c0 = tx * 4;
    long base = (long)blockIdx.x * 512;

    const float4* rbf4 = reinterpret_cast<const float4*>(rbf);

    int cur_i = -1;
    float racc[4] = {0.f, 0.f, 0.f, 0.f};

    float4 pre[4];
#pragma unroll
    for (int s = 0; s < 4; ++s) {
        int idx = tid + s * 256;
        long e = base + (idx >> 4);
        pre[s] = (e < E_) ? rbf4[e * 16 + (idx & 15)]
                          : make_float4(0.f, 0.f, 0.f, 0.f);
    }

    for (int t = 0; t < 8; ++t) {
        __syncthreads();
#pragma unroll
        for (int s = 0; s < 4; ++s) {
            int idx = tid + s * 256;
            int er = idx >> 4;
            int k4 = idx & 15;
            u64 hv, lv;
            split4(pre[s], hv, lv);
            uint32_t off = (uint32_t)(er * ELDK + k4 * 4) * 2;
            *reinterpret_cast<u64*>(sm + ESM_AHI + off) = hv;
            *reinterpret_cast<u64*>(sm + ESM_ALO + off) = lv;
        }
        __syncthreads();

        if (t < 7) {
#pragma unroll
            for (int s = 0; s < 4; ++s) {
                int idx = tid + s * 256;
                long e = base + (t + 1) * 64 + (idx >> 4);
                pre[s] = (e < E_) ? rbf4[e * 16 + (idx & 15)]
                                  : make_float4(0.f, 0.f, 0.f, 0.f);
            }
        }

        float d[2][4][4];
#pragma unroll
        for (int mt = 0; mt < 2; ++mt)
#pragma unroll
            for (int nt = 0; nt < 4; ++nt)
#pragma unroll
                for (int q = 0; q < 4; ++q) d[mt][nt][q] = 0.f;

#pragma unroll
        for (int ks = 0; ks < 4; ++ks) {
            int kb = ks * 16;
            unsigned bh[2][4], bl[2][4], ah[2][4], al[2][4];
#pragma unroll
            for (int p = 0; p < 2; ++p) {
                uint32_t boff =
                    (uint32_t)((b_n + p * 16) * ELDK + kb + b_k8) * 2;
                ldsm4(bh[p], smb + ESM_WHI + boff);
                ldsm4(bl[p], smb + ESM_WLO + boff);
            }
#pragma unroll
            for (int mt = 0; mt < 2; ++mt) {
                uint32_t aoff =
                    (uint32_t)((a_row + mt * 16) * ELDK + kb + a_k8) * 2;
                ldsm4(ah[mt], smb + ESM_AHI + aoff);
                ldsm4(al[mt], smb + ESM_ALO + aoff);
            }
#pragma unroll
            for (int term = 0; term < 3; ++term) {
#pragma unroll
                for (int mt = 0; mt < 2; ++mt) {
#pragma unroll
                    for (int nt = 0; nt < 4; ++nt) {
                        const unsigned* af = (term == 2) ? al[mt] : ah[mt];
                        const unsigned* bf =
                            (term == 1) ? bl[nt >> 1] : bh[nt >> 1];
                        mma16816(d[mt][nt], af, bf[(nt & 1) * 2],
                                 bf[(nt & 1) * 2 + 1]);
                    }
                }
            }
        }

#pragma unroll
        for (int mt = 0; mt < 2; ++mt)
#pragma unroll
            for (int half = 0; half < 2; ++half) {
                int row = warp_m * 32 + mt * 16 + (lane >> 2) + half * 8;
#pragma unroll
                for (int nt = 0; nt < 4; ++nt) {
                    int col = warp_n * 32 + nt * 8 + (lane & 3) * 2;
                    float2 v;
                    v.x = d[mt][nt][half * 2 + 0];
                    v.y = d[mt][nt][half * 2 + 1];
                    *reinterpret_cast<float2*>(
                        sm + ESM_G + (uint32_t)(row * EG_LD + col) * 4) = v;
                }
            }
        __syncthreads();

        int iarr[8];
        float4 xv[8];
#pragma unroll
        for (int s = 0; s < 8; ++s) {
            long e = base + t * 64 + eg * 8 + s;
            if (e < E_) {
                iarr[s] = __ldg(ii + e);
                int j = __ldg(jj + e);
                xv[s] = __ldg(reinterpret_cast<const float4*>(
                                  xjall + (size_t)j * 128) + tx);
            } else {
                iarr[s] = -1;
                xv[s] = make_float4(0.f, 0.f, 0.f, 0.f);
            }
        }
#pragma unroll
        for (int s = 0; s < 8; ++s) {
            if (iarr[s] < 0) continue;
            float4 g4 = *reinterpret_cast<const float4*>(
                sm + ESM_G + (uint32_t)((eg * 8 + s) * EG_LD + c0) * 4);
            float v0 = g4.x * xv[s].x;
            float v1 = g4.y * xv[s].y;
            float v2 = g4.z * xv[s].z;
            float v3 = g4.w * xv[s].w;
            if (iarr[s] != cur_i) {
                if (cur_i >= 0) {
                    float* dst = mout + (size_t)cur_i * 128 + c0;
                    atomicAdd(dst + 0, racc[0]);
                    atomicAdd(dst + 1, racc[1]);
                    atomicAdd(dst + 2, racc[2]);
                    atomicAdd(dst + 3, racc[3]);
                }
                cur_i = iarr[s];
                racc[0] = v0; racc[1] = v1; racc[2] = v2; racc[3] = v3;
            } else {
                racc[0] += v0; racc[1] += v1; racc[2] += v2; racc[3] += v3;
            }
        }
    }
    if (cur_i >= 0) {
        float* dst = mout + (size_t)cur_i * 128 + c0;
        atomicAdd(dst + 0, racc[0]);
        atomicAdd(dst + 1, racc[1]);
        atomicAdd(dst + 2, racc[2]);
        atomicAdd(dst + 3, racc[3]);
    }
}

// ---------------------------------------------------------------------------
// Launch
// ---------------------------------------------------------------------------
extern "C" void kernel_launch(void* const* d_in, const int* in_sizes, int n_in,
                              void* d_out, int out_size) {
    const float* x    = (const float*)d_in[0];
    const float* rbf  = (const float*)d_in[1];
    const float* Wk2f = (const float*)d_in[2];
    const float* Wi   = (const float*)d_in[3];
    const float* bi   = (const float*)d_in[4];
    const float* Wj   = (const float*)d_in[5];
    const float* bj   = (const float*)d_in[6];
    const float* Wr1  = (const float*)d_in[7];
    const float* br1  = (const float*)d_in[8];
    const float* Wr2  = (const float*)d_in[9];
    const float* br2  = (const float*)d_in[10];
    const float* Wf   = (const float*)d_in[11];
    const float* bfb  = (const float*)d_in[12];
    const float* u    = (const float*)d_in[13];
    const int* idx_i  = (const int*)d_in[14];
    const int* idx_j  = (const int*)d_in[15];
    float* out = (float*)d_out;

    void *p_m, *p_xjall, *p_hi, *p_lo, *p_wkh, *p_wkl;
    cudaGetSymbolAddress(&p_m, g_m);
    cudaGetSymbolAddress(&p_xjall, g_xjall);
    cudaGetSymbolAddress(&p_hi, g_wthi);
    cudaGetSymbolAddress(&p_lo, g_wtlo);
    cudaGetSymbolAddress(&p_wkh, g_wkhi);
    cudaGetSymbolAddress(&p_wkl, g_wklo);
    float* m = (float*)p_m;
    float* xjall = (float*)p_xjall;
    __nv_bfloat16* whi = (__nv_bfloat16*)p_hi;
    __nv_bfloat16* wlo = (__nv_bfloat16*)p_lo;
    __nv_bfloat16* wkhi = (__nv_bfloat16*)p_wkh;
    __nv_bfloat16* wklo = (__nv_bfloat16*)p_wkl;

    cudaFuncSetAttribute(head_kernel,
                         cudaFuncAttributeMaxDynamicSharedMemorySize, SM_TOTAL);
    cudaFuncSetAttribute(tail_kernel,
                         cudaFuncAttributeMaxDynamicSharedMemorySize, SM_TOTAL);
    cudaFuncSetAttribute(edge_mma,
                         cudaFuncAttributeMaxDynamicSharedMemorySize, ESM_TOTAL);

    // one-time weight packing
    dim3 pw(64, 9);
    packw_kernel<<<pw, 256>>>(Wi, Wj, Wr1, Wr2, Wf, whi, wlo);
    packwk_kernel<<<32, 256>>>(Wk2f, wkhi, wklo);

    int node_blocks = (N_ + 63) / 64;     // 782
    int edge_blocks = (E_ + 511) / 512;   // 1563

    // m = ssp(ssp(x)@Wi+bi); xjall = ssp(ssp(x)@Wj+bj)
    head_kernel<<<node_blocks, 256, SM_TOTAL>>>(x, whi, wlo, bi, bj,
                                                m, xjall, N_);
    // m += segment_sum((rbf@Wk2f) * xjall[idx_j], idx_i)
    edge_mma<<<edge_blocks, 256, ESM_TOTAL>>>(rbf, wkhi, wklo, xjall,
                                              idx_i, idx_j, m);
    // fused residual chain + final projection (m in global, act in smem)
    tail_kernel<<<node_blocks, 256, SM_TOTAL>>>(m, whi, wlo, br1, br2, bfb,
                                                x, u, out, N_);
}